// round 1
// baseline (speedup 1.0000x reference)
#include <cuda_runtime.h>
#include <stdint.h>

// Problem constants (shape-fixed per dataset): B=4, C=128, N_IN=163842, N_OUT=40962
#define BDIM 4
#define CDIM 128
#define EPSV 1e-8f

// Scratch: denominator accumulator (N_OUT <= 65536)
__device__ float g_denom[65536];
// Flag: 1 if parent_idx is int64, 0 if int32
__device__ int g_idx64;

// ---------------------------------------------------------------------------
// Detect parent_idx dtype. Values are in [0, 40962) (< 2^31, non-negative).
// If stored as int64 (little-endian), every odd 32-bit word is 0.
// If stored as int32, odd words are independent random indices; 16 of them
// all being zero has probability ~(1/40962)^16 ~= 0.
// ---------------------------------------------------------------------------
__global__ void detect_idx_kernel(const void* __restrict__ parent) {
    const int* p32 = (const int*)parent;
    int all_zero = 1;
#pragma unroll
    for (int k = 0; k < 16; k++) {
        if (p32[2 * k + 1] != 0) all_zero = 0;
    }
    g_idx64 = all_zero;
}

// ---------------------------------------------------------------------------
// Zero the output accumulator (d_out) and the denom scratch.
// ---------------------------------------------------------------------------
__global__ void zero_kernel(float4* __restrict__ out, int total4, int n_out) {
    int idx = blockIdx.x * blockDim.x + threadIdx.x;
    if (idx < total4) out[idx] = make_float4(0.f, 0.f, 0.f, 0.f);
    if (idx < n_out) g_denom[idx] = 0.f;
}

// ---------------------------------------------------------------------------
// Scatter: one warp per input vertex, lane = channel-quad (32 quads of 4 = 128 ch).
// Each lane does 4 coalesced float4 loads (one per batch) and 4 vectorized
// red.global.add.v4.f32 into the L2-resident accumulator.
// Lane 0 also accumulates the denominator.
// ---------------------------------------------------------------------------
__global__ void scatter_kernel(const float* __restrict__ x,
                               const float* __restrict__ omega,
                               const void* __restrict__ parent,
                               float* __restrict__ out,
                               int n_in, int n_out) {
    int gid = blockIdx.x * blockDim.x + threadIdx.x;
    int i = gid >> 5;       // vertex
    int g = gid & 31;       // channel quad
    if (i >= n_in) return;

    long long p;
    if (g_idx64) {
        p = ((const long long*)parent)[i];
    } else {
        p = (long long)(((const int*)parent)[i]);
    }
    float w = omega[i];

    if (g == 0) {
        atomicAdd(&g_denom[(int)p], w);
    }

    const float4* x4 = (const float4*)x;
#pragma unroll
    for (int b = 0; b < BDIM; b++) {
        // element offset (b*n_in + i)*C + g*4  ->  float4 index (b*n_in + i)*32 + g
        float4 v = x4[((long long)(b * n_in + i)) * 32 + g];
        float rx = v.x * w, ry = v.y * w, rz = v.z * w, rw = v.w * w;
        float* dst = out + (((long long)b * n_out + p) * CDIM + (g << 2));
        asm volatile("red.global.add.v4.f32 [%0], {%1,%2,%3,%4};"
                     :: "l"(dst), "f"(rx), "f"(ry), "f"(rz), "f"(rw)
                     : "memory");
    }
}

// ---------------------------------------------------------------------------
// Normalize: out[b, p, :] /= max(denom[p], eps).
// 32 consecutive float4 indices share one p -> denom load broadcasts per warp.
// ---------------------------------------------------------------------------
__global__ void divide_kernel(float4* __restrict__ out, int n_out, int total4) {
    int idx = blockIdx.x * blockDim.x + threadIdx.x;
    if (idx >= total4) return;
    int p = (idx >> 5) % n_out;
    float inv = 1.0f / fmaxf(g_denom[p], EPSV);
    float4 v = out[idx];
    v.x *= inv; v.y *= inv; v.z *= inv; v.w *= inv;
    out[idx] = v;
}

// ---------------------------------------------------------------------------
// Launch: detect -> zero -> scatter(+denom) -> divide. All on the default
// stream, no syncs, no allocations: graph-capturable.
// Inputs (metadata order): x [B,N_in,C] f32, omega [N_in] f32,
// parent_idx [N_in] int32/int64, n_out scalar (unused; derived from out_size).
// ---------------------------------------------------------------------------
extern "C" void kernel_launch(void* const* d_in, const int* in_sizes, int n_in_args,
                              void* d_out, int out_size) {
    const float* x      = (const float*)d_in[0];
    const float* omega  = (const float*)d_in[1];
    const void*  parent = d_in[2];

    int n_in  = in_sizes[1];                 // omega element count = N_in
    int n_out = out_size / (BDIM * CDIM);    // 40962
    int total4 = out_size / 4;               // float4 count of output

    detect_idx_kernel<<<1, 1>>>(parent);

    {
        int blk = 256;
        int grd = (total4 + blk - 1) / blk;
        zero_kernel<<<grd, blk>>>((float4*)d_out, total4, n_out);
    }
    {
        int threads = n_in * 32;
        int blk = 256;
        int grd = (threads + blk - 1) / blk;
        scatter_kernel<<<grd, blk>>>(x, omega, parent, (float*)d_out, n_in, n_out);
    }
    {
        int blk = 256;
        int grd = (total4 + blk - 1) / blk;
        divide_kernel<<<grd, blk>>>((float4*)d_out, n_out, total4);
    }
}